// round 8
// baseline (speedup 1.0000x reference)
#include <cuda_runtime.h>
#include <math.h>

#define NK      10000
#define SEQ     512
#define KSMAX   11
#define SH_LEN  2048     // max read index proven <= ~1886
#define TPB     128
#define GL      8        // lanes per (batch-pair, kernel)
#define PREP_T  1024
#define PBINS   6144     // key = clamp(d,0,95)*64 + min(L>>4,63)

__device__ int g_padmax;
__device__ int g_perm[NK];

__device__ __forceinline__ int sort_key(int d, int L) {
    if (d < 0) d = 0;
    if (d > 95) d = 95;
    int lb = L >> 4;
    if (lb < 0) lb = 0;
    if (lb > 63) lb = 63;
    return d * 64 + lb;
}

// ---- single fused prep kernel: padmax + counting sort by (dil, lo-bucket) ----
__global__ __launch_bounds__(PREP_T) void prep_fused_kernel(
    const int* __restrict__ base,
    const int* __restrict__ dil,
    const int* __restrict__ lo)
{
    __shared__ int sbins[PBINS];
    __shared__ int spart[PREP_T];
    const int tid = threadIdx.x;

    int m = 0;
    for (int i = tid; i < NK; i += PREP_T) m = max(m, base[i]);
#pragma unroll
    for (int o = 16; o > 0; o >>= 1) m = max(m, __shfl_xor_sync(0xffffffffu, m, o));
    if ((tid & 31) == 0) spart[tid >> 5] = m;
    __syncthreads();
    if (tid == 0) {
        int mm = 0;
        for (int w = 0; w < PREP_T / 32; w++) mm = max(mm, spart[w]);
        g_padmax = mm;
    }

    for (int i = tid; i < PBINS; i += PREP_T) sbins[i] = 0;
    __syncthreads();

    for (int i = tid; i < NK; i += PREP_T)
        atomicAdd(&sbins[sort_key(dil[i], lo[i])], 1);
    __syncthreads();

    int s = 0;
#pragma unroll
    for (int j = 0; j < 6; j++) s += sbins[tid * 6 + j];
    spart[tid] = s;
    __syncthreads();
    for (int off = 1; off < PREP_T; off <<= 1) {
        int v = spart[tid];
        int u = (tid >= off) ? spart[tid - off] : 0;
        __syncthreads();
        spart[tid] = v + u;
        __syncthreads();
    }
    int run = (tid > 0) ? spart[tid - 1] : 0;
#pragma unroll
    for (int j = 0; j < 6; j++) {
        int c = sbins[tid * 6 + j];
        sbins[tid * 6 + j] = run;
        run += c;
    }
    __syncthreads();

    for (int i = tid; i < NK; i += PREP_T) {
        int pos = atomicAdd(&sbins[sort_key(dil[i], lo[i])], 1);
        g_perm[pos] = i;
    }
}

// one ring trip at static rotation u: 1 LDS.64 + 22 FMA + 2 FMNMX + 2 cnt
#define RING_TRIP(u)                                                        \
    do {                                                                    \
        const float2 nv = *ptr; ptr += d;                                   \
        y[(10 + (u)) % KSMAX] = nv;                                         \
        float a0 = bias, a1 = bias;                                         \
        _Pragma("unroll")                                                   \
        for (int j = 0; j < KSMAX; j++) {                                   \
            const float2 yy = y[((u) + j) % KSMAX];                         \
            a0 = fmaf(w[j], yy.x, a0);                                      \
            a1 = fmaf(w[j], yy.y, a1);                                      \
        }                                                                   \
        max0 = fmaxf(max0, a0);                                             \
        max1 = fmaxf(max1, a1);                                             \
        cnt0 += (a0 > 0.0f) ? 1 : 0;                                        \
        cnt1 += (a1 > 0.0f) ? 1 : 0;                                        \
    } while (0)

#define TSEQ1  RING_TRIP(0);
#define TSEQ2  TSEQ1 RING_TRIP(1);
#define TSEQ3  TSEQ2 RING_TRIP(2);
#define TSEQ4  TSEQ3 RING_TRIP(3);
#define TSEQ5  TSEQ4 RING_TRIP(4);
#define TSEQ6  TSEQ5 RING_TRIP(5);
#define TSEQ7  TSEQ6 RING_TRIP(6);
#define TSEQ8  TSEQ7 RING_TRIP(7);
#define TSEQ9  TSEQ8 RING_TRIP(8);
#define TSEQ10 TSEQ9 RING_TRIP(9);

// ring over one strided stream: full 11-chunks unconditional; tail via a
// jump-table switch to a straight-line block of exactly n trips (no per-trip
// compare/branch, one BRX per segment, warp-converged under the sort).
__device__ __forceinline__ void ring_run(
    const float2* __restrict__ p, int n, int d,
    const float w[KSMAX], float bias,
    float& max0, float& max1, int& cnt0, int& cnt1)
{
    float2 y[KSMAX];
#pragma unroll
    for (int j = 0; j < 10; j++) y[j] = p[j * d];
    const float2* ptr = p + 10 * d;

    while (n >= KSMAX) {
#pragma unroll
        for (int u = 0; u < KSMAX; u++) RING_TRIP(u);
        n -= KSMAX;
    }
    switch (n) {
        case 1:  { TSEQ1 }  break;
        case 2:  { TSEQ2 }  break;
        case 3:  { TSEQ3 }  break;
        case 4:  { TSEQ4 }  break;
        case 5:  { TSEQ5 }  break;
        case 6:  { TSEQ6 }  break;
        case 7:  { TSEQ7 }  break;
        case 8:  { TSEQ8 }  break;
        case 9:  { TSEQ9 }  break;
        case 10: { TSEQ10 } break;
        default: break;
    }
}

// ---- main kernel: 8 lanes per (batch-pair, kernel); lane s owns outputs
// [s*L/8, (s+1)*L/8) in flattened (phase, q) order -> exact balance.
__global__ __launch_bounds__(TPB) void rocket_main_kernel(
    const float* __restrict__ x,
    const float* __restrict__ W,
    const float* __restrict__ Bias,
    const int*   __restrict__ base,
    const int*   __restrict__ dil,
    const int*   __restrict__ lo,
    float*       __restrict__ out)
{
    __shared__ float2 sh[SH_LEN];   // 16KB
    const int b0  = 2 * blockIdx.y;
    const int tid = threadIdx.x;
    const int padmax = g_padmax;

    for (int i = tid; i < SH_LEN; i += TPB) sh[i] = make_float2(0.0f, 0.0f);
    __syncthreads();
    for (int i = tid; i < SEQ; i += TPB)
        sh[padmax + i] = make_float2(x[b0 * SEQ + i], x[(b0 + 1) * SEQ + i]);
    __syncthreads();

    const int idx  = blockIdx.x * TPB + tid;     // 0 .. 8*NK-1 exactly
    const int slot = idx >> 3;
    const int s    = idx & 7;
    const int k    = g_perm[NK - 1 - slot];      // largest-d first

    float w[KSMAX];
#pragma unroll
    for (int j = 0; j < KSMAX; j++) w[j] = W[k * KSMAX + j];
    const float bias = Bias[k];
    const int bs = base[k];
    const int d  = dil[k];
    const int L  = lo[k];

    // per-kernel phase geometry: nq(r) = q0+1 for r<=rem else q0
    const int q0  = (L - 1) / d;
    const int rem = (L - 1) - q0 * d;

    // lane output range [c_lo, c_hi) in flattened (phase,q) order
    const int c_lo = (s * L) >> 3;
    const int c_hi = ((s + 1) * L) >> 3;

    // locate start (r, q) such that cumulative-outputs-before == c_lo
    int r, q;
    {
        const int np  = q0 + 1;
        const int thr = (rem + 1) * np;
        if (c_lo < thr) { r = c_lo / np; q = c_lo - r * np; }
        else {
            const int c2 = c_lo - thr;
            const int rr = c2 / q0;
            r = rem + 1 + rr;
            q = c2 - rr * q0;
        }
    }

    float max0 = -INFINITY, max1 = -INFINITY;
    int   cnt0 = 0, cnt1 = 0;

    int left = c_hi - c_lo;
    while (left > 0) {
        const int nq_r = (r <= rem) ? (q0 + 1) : q0;
        const int n = min(nq_r - q, left);
        ring_run(sh + bs + r + q * d, n, d, w, bias, max0, max1, cnt0, cnt1);
        left -= n;
        ++r;
        q = 0;
    }

    // combine the 8-lane group
    const unsigned mask = 0xffffffffu;
#pragma unroll
    for (int o = 1; o <= 4; o <<= 1) {
        max0 = fmaxf(max0, __shfl_xor_sync(mask, max0, o));
        max1 = fmaxf(max1, __shfl_xor_sync(mask, max1, o));
        cnt0 += __shfl_xor_sync(mask, cnt0, o);
        cnt1 += __shfl_xor_sync(mask, cnt1, o);
    }

    if (s == 0) {
        const float invL = 1.0f / (float)L;
        float2* o0p = (float2*)(out + (size_t)b0 * (2 * NK) + 2 * k);
        float2* o1p = (float2*)(out + (size_t)(b0 + 1) * (2 * NK) + 2 * k);
        *o0p = make_float2(max0, (float)cnt0 * invL);
        *o1p = make_float2(max1, (float)cnt1 * invL);
    }
}

extern "C" void kernel_launch(void* const* d_in, const int* in_sizes, int n_in,
                              void* d_out, int out_size) {
    const float* x    = (const float*)d_in[0];
    const float* Wt   = (const float*)d_in[1];
    const float* Bias = (const float*)d_in[2];
    const int*   base = (const int*)d_in[3];
    const int*   dil  = (const int*)d_in[4];
    const int*   lo   = (const int*)d_in[5];
    float* out = (float*)d_out;

    prep_fused_kernel<<<1, PREP_T>>>(base, dil, lo);

    const int nblk = (GL * NK) / TPB;   // 625 exactly
    dim3 grid(nblk, 4);
    rocket_main_kernel<<<grid, TPB>>>(x, Wt, Bias, base, dil, lo, out);
}

// round 9
// speedup vs baseline: 1.2511x; 1.2511x over previous
#include <cuda_runtime.h>
#include <math.h>

#define NK      10000
#define SEQ     512
#define KSMAX   11
#define SH_LEN  2048     // max read index proven <= ~1886
#define TPB     128
#define GL      16       // lanes per (batch-quad, kernel)
#define PREP_T  1024
#define PBINS   6144     // key = clamp(d,0,95)*64 + min(L>>4,63)

__device__ int g_padmax;
__device__ int g_perm[NK];

__device__ __forceinline__ int sort_key(int d, int L) {
    if (d < 0) d = 0;
    if (d > 95) d = 95;
    int lb = L >> 4;
    if (lb < 0) lb = 0;
    if (lb > 63) lb = 63;
    return d * 64 + lb;
}

// ---- single fused prep kernel: padmax + counting sort by (dil, lo-bucket) ----
__global__ __launch_bounds__(PREP_T) void prep_fused_kernel(
    const int* __restrict__ base,
    const int* __restrict__ dil,
    const int* __restrict__ lo)
{
    __shared__ int sbins[PBINS];
    __shared__ int spart[PREP_T];
    const int tid = threadIdx.x;

    int m = 0;
    for (int i = tid; i < NK; i += PREP_T) m = max(m, base[i]);
#pragma unroll
    for (int o = 16; o > 0; o >>= 1) m = max(m, __shfl_xor_sync(0xffffffffu, m, o));
    if ((tid & 31) == 0) spart[tid >> 5] = m;
    __syncthreads();
    if (tid == 0) {
        int mm = 0;
        for (int w = 0; w < PREP_T / 32; w++) mm = max(mm, spart[w]);
        g_padmax = mm;
    }

    for (int i = tid; i < PBINS; i += PREP_T) sbins[i] = 0;
    __syncthreads();

    for (int i = tid; i < NK; i += PREP_T)
        atomicAdd(&sbins[sort_key(dil[i], lo[i])], 1);
    __syncthreads();

    int s = 0;
#pragma unroll
    for (int j = 0; j < 6; j++) s += sbins[tid * 6 + j];
    spart[tid] = s;
    __syncthreads();
    for (int off = 1; off < PREP_T; off <<= 1) {
        int v = spart[tid];
        int u = (tid >= off) ? spart[tid - off] : 0;
        __syncthreads();
        spart[tid] = v + u;
        __syncthreads();
    }
    int run = (tid > 0) ? spart[tid - 1] : 0;
#pragma unroll
    for (int j = 0; j < 6; j++) {
        int c = sbins[tid * 6 + j];
        sbins[tid * 6 + j] = run;
        run += c;
    }
    __syncthreads();

    for (int i = tid; i < NK; i += PREP_T) {
        int pos = atomicAdd(&sbins[sort_key(dil[i], lo[i])], 1);
        g_perm[pos] = i;
    }
}

// one ring trip at static rotation u: 1 LDS.128 + 44 FMA + 4 FMNMX + 4 cnt
#define RING_TRIP(u)                                                        \
    do {                                                                    \
        const float4 nv = *ptr; ptr += d;                                   \
        y[(10 + (u)) % KSMAX] = nv;                                         \
        float a0 = bias, a1 = bias, a2 = bias, a3 = bias;                   \
        _Pragma("unroll")                                                   \
        for (int j = 0; j < KSMAX; j++) {                                   \
            const float4 yy = y[((u) + j) % KSMAX];                         \
            a0 = fmaf(w[j], yy.x, a0);                                      \
            a1 = fmaf(w[j], yy.y, a1);                                      \
            a2 = fmaf(w[j], yy.z, a2);                                      \
            a3 = fmaf(w[j], yy.w, a3);                                      \
        }                                                                   \
        max0 = fmaxf(max0, a0);                                             \
        max1 = fmaxf(max1, a1);                                             \
        max2 = fmaxf(max2, a2);                                             \
        max3 = fmaxf(max3, a3);                                             \
        cnt0 += (a0 > 0.0f) ? 1 : 0;                                        \
        cnt1 += (a1 > 0.0f) ? 1 : 0;                                        \
        cnt2 += (a2 > 0.0f) ? 1 : 0;                                        \
        cnt3 += (a3 > 0.0f) ? 1 : 0;                                        \
    } while (0)

// ring over one strided stream: full 11-chunks unconditional; tail via
// unrolled break-loop (round-7 proven form).
__device__ __forceinline__ void ring_run(
    const float4* __restrict__ p, int n, int d,
    const float w[KSMAX], float bias,
    float& max0, float& max1, float& max2, float& max3,
    int& cnt0, int& cnt1, int& cnt2, int& cnt3)
{
    float4 y[KSMAX];
#pragma unroll
    for (int j = 0; j < 10; j++) y[j] = p[j * d];
    const float4* ptr = p + 10 * d;

    while (n >= KSMAX) {
#pragma unroll
        for (int u = 0; u < KSMAX; u++) RING_TRIP(u);
        n -= KSMAX;
    }
#pragma unroll
    for (int u = 0; u < KSMAX - 1; u++) {
        if (u >= n) break;      // near-uniform within warp (sorted work)
        RING_TRIP(u);
    }
}

// ---- main kernel: 16 lanes per (batch-quad, kernel); lane s owns outputs
// [s*L/16, (s+1)*L/16) in flattened (phase, q) order -> exact balance.
__global__ __launch_bounds__(TPB, 5) void rocket_main_kernel(
    const float* __restrict__ x,
    const float* __restrict__ W,
    const float* __restrict__ Bias,
    const int*   __restrict__ base,
    const int*   __restrict__ dil,
    const int*   __restrict__ lo,
    float*       __restrict__ out)
{
    __shared__ float4 sh[SH_LEN];   // 32KB
    const int b0  = 4 * blockIdx.y;
    const int tid = threadIdx.x;
    const int padmax = g_padmax;

    for (int i = tid; i < SH_LEN; i += TPB) sh[i] = make_float4(0.f, 0.f, 0.f, 0.f);
    __syncthreads();
    for (int i = tid; i < SEQ; i += TPB)
        sh[padmax + i] = make_float4(x[(b0 + 0) * SEQ + i], x[(b0 + 1) * SEQ + i],
                                     x[(b0 + 2) * SEQ + i], x[(b0 + 3) * SEQ + i]);
    __syncthreads();

    const int idx  = blockIdx.x * TPB + tid;     // 0 .. 16*NK-1 exactly
    const int slot = idx >> 4;
    const int s    = idx & 15;
    const int k    = g_perm[NK - 1 - slot];      // largest-d first

    float w[KSMAX];
#pragma unroll
    for (int j = 0; j < KSMAX; j++) w[j] = W[k * KSMAX + j];
    const float bias = Bias[k];
    const int bs = base[k];
    const int d  = dil[k];
    const int L  = lo[k];

    // per-kernel phase geometry: nq(r) = q0+1 for r<=rem else q0
    const int q0  = (L - 1) / d;
    const int rem = (L - 1) - q0 * d;

    // lane output range [c_lo, c_hi) in flattened (phase,q) order
    const int c_lo = (s * L) >> 4;
    const int c_hi = ((s + 1) * L) >> 4;

    // locate start (r, q) with cumulative-outputs-before == c_lo
    int r, q;
    {
        const int np  = q0 + 1;
        const int thr = (rem + 1) * np;
        if (c_lo < thr) { r = c_lo / np; q = c_lo - r * np; }
        else {
            const int c2 = c_lo - thr;
            const int rr = c2 / q0;
            r = rem + 1 + rr;
            q = c2 - rr * q0;
        }
    }

    float max0 = -INFINITY, max1 = -INFINITY, max2 = -INFINITY, max3 = -INFINITY;
    int   cnt0 = 0, cnt1 = 0, cnt2 = 0, cnt3 = 0;

    int left = c_hi - c_lo;
    while (left > 0) {
        const int nq_r = (r <= rem) ? (q0 + 1) : q0;
        const int n = min(nq_r - q, left);
        ring_run(sh + bs + r + q * d, n, d, w, bias,
                 max0, max1, max2, max3, cnt0, cnt1, cnt2, cnt3);
        left -= n;
        ++r;
        q = 0;
    }

    // combine the 16-lane group
    const unsigned mask = 0xffffffffu;
#pragma unroll
    for (int o = 1; o <= 8; o <<= 1) {
        max0 = fmaxf(max0, __shfl_xor_sync(mask, max0, o));
        max1 = fmaxf(max1, __shfl_xor_sync(mask, max1, o));
        max2 = fmaxf(max2, __shfl_xor_sync(mask, max2, o));
        max3 = fmaxf(max3, __shfl_xor_sync(mask, max3, o));
        cnt0 += __shfl_xor_sync(mask, cnt0, o);
        cnt1 += __shfl_xor_sync(mask, cnt1, o);
        cnt2 += __shfl_xor_sync(mask, cnt2, o);
        cnt3 += __shfl_xor_sync(mask, cnt3, o);
    }

    if (s == 0) {
        const float invL = 1.0f / (float)L;
        float2* o0 = (float2*)(out + (size_t)(b0 + 0) * (2 * NK) + 2 * k);
        float2* o1 = (float2*)(out + (size_t)(b0 + 1) * (2 * NK) + 2 * k);
        float2* o2 = (float2*)(out + (size_t)(b0 + 2) * (2 * NK) + 2 * k);
        float2* o3 = (float2*)(out + (size_t)(b0 + 3) * (2 * NK) + 2 * k);
        *o0 = make_float2(max0, (float)cnt0 * invL);
        *o1 = make_float2(max1, (float)cnt1 * invL);
        *o2 = make_float2(max2, (float)cnt2 * invL);
        *o3 = make_float2(max3, (float)cnt3 * invL);
    }
}

extern "C" void kernel_launch(void* const* d_in, const int* in_sizes, int n_in,
                              void* d_out, int out_size) {
    const float* x    = (const float*)d_in[0];
    const float* Wt   = (const float*)d_in[1];
    const float* Bias = (const float*)d_in[2];
    const int*   base = (const int*)d_in[3];
    const int*   dil  = (const int*)d_in[4];
    const int*   lo   = (const int*)d_in[5];
    float* out = (float*)d_out;

    prep_fused_kernel<<<1, PREP_T>>>(base, dil, lo);

    const int nblk = (GL * NK) / TPB;   // 1250 exactly
    dim3 grid(nblk, 2);
    rocket_main_kernel<<<grid, TPB>>>(x, Wt, Bias, base, dil, lo, out);
}

// round 10
// speedup vs baseline: 1.3363x; 1.0681x over previous
#include <cuda_runtime.h>
#include <math.h>

#define NK      10000
#define SEQ     512
#define KSMAX   11
#define SH_LEN  2048     // max read index proven <= ~1886
#define TPB     128
#define GL      16       // lanes per (batch-quad, kernel)
#define PREP_T  1024
#define PBINS   6144     // key = clamp(d,0,95)*64 + min(L>>4,63)

__device__ int g_padmax;
__device__ int g_perm[NK];

// packed fp32x2 helpers (sm_103a)
#define FMA2(acc, ww, yy) \
    asm("fma.rn.f32x2 %0, %1, %2, %0;" : "+l"(acc) : "l"(ww), "l"(yy))
#define UNPACK2(lo, hi, in) \
    asm("mov.b64 {%0, %1}, %2;" : "=f"(lo), "=f"(hi) : "l"(in))
#define PACK2(out, lo, hi) \
    asm("mov.b64 %0, {%1, %2};" : "=l"(out) : "f"(lo), "f"(hi))

__device__ __forceinline__ int sort_key(int d, int L) {
    if (d < 0) d = 0;
    if (d > 95) d = 95;
    int lb = L >> 4;
    if (lb < 0) lb = 0;
    if (lb > 63) lb = 63;
    return d * 64 + lb;
}

// ---- single fused prep kernel: padmax + counting sort by (dil, lo-bucket) ----
__global__ __launch_bounds__(PREP_T) void prep_fused_kernel(
    const int* __restrict__ base,
    const int* __restrict__ dil,
    const int* __restrict__ lo)
{
    __shared__ int sbins[PBINS];
    __shared__ int spart[PREP_T];
    const int tid = threadIdx.x;

    int m = 0;
    for (int i = tid; i < NK; i += PREP_T) m = max(m, base[i]);
#pragma unroll
    for (int o = 16; o > 0; o >>= 1) m = max(m, __shfl_xor_sync(0xffffffffu, m, o));
    if ((tid & 31) == 0) spart[tid >> 5] = m;
    __syncthreads();
    if (tid == 0) {
        int mm = 0;
        for (int w = 0; w < PREP_T / 32; w++) mm = max(mm, spart[w]);
        g_padmax = mm;
    }

    for (int i = tid; i < PBINS; i += PREP_T) sbins[i] = 0;
    __syncthreads();

    for (int i = tid; i < NK; i += PREP_T)
        atomicAdd(&sbins[sort_key(dil[i], lo[i])], 1);
    __syncthreads();

    int s = 0;
#pragma unroll
    for (int j = 0; j < 6; j++) s += sbins[tid * 6 + j];
    spart[tid] = s;
    __syncthreads();
    for (int off = 1; off < PREP_T; off <<= 1) {
        int v = spart[tid];
        int u = (tid >= off) ? spart[tid - off] : 0;
        __syncthreads();
        spart[tid] = v + u;
        __syncthreads();
    }
    int run = (tid > 0) ? spart[tid - 1] : 0;
#pragma unroll
    for (int j = 0; j < 6; j++) {
        int c = sbins[tid * 6 + j];
        sbins[tid * 6 + j] = run;
        run += c;
    }
    __syncthreads();

    for (int i = tid; i < NK; i += PREP_T) {
        int pos = atomicAdd(&sbins[sort_key(dil[i], lo[i])], 1);
        g_perm[pos] = i;
    }
}

// one ring trip at static rotation u:
// 1 LDS.128 + 22 FFMA2 (44 fp32 FMA) + 2 unpack + 4 FMNMX + 4 cnt
#define RING_TRIP(u)                                                        \
    do {                                                                    \
        const ulonglong2 nv = *ptr; ptr += d;                               \
        y01[(10 + (u)) % KSMAX] = nv.x;                                     \
        y23[(10 + (u)) % KSMAX] = nv.y;                                     \
        unsigned long long acc01 = bias2, acc23 = bias2;                    \
        _Pragma("unroll")                                                   \
        for (int j = 0; j < KSMAX; j++) {                                   \
            FMA2(acc01, w2[j], y01[((u) + j) % KSMAX]);                     \
            FMA2(acc23, w2[j], y23[((u) + j) % KSMAX]);                     \
        }                                                                   \
        float a0, a1, a2, a3;                                               \
        UNPACK2(a0, a1, acc01);                                             \
        UNPACK2(a2, a3, acc23);                                             \
        max0 = fmaxf(max0, a0);                                             \
        max1 = fmaxf(max1, a1);                                             \
        max2 = fmaxf(max2, a2);                                             \
        max3 = fmaxf(max3, a3);                                             \
        cnt0 += (a0 > 0.0f) ? 1 : 0;                                        \
        cnt1 += (a1 > 0.0f) ? 1 : 0;                                        \
        cnt2 += (a2 > 0.0f) ? 1 : 0;                                        \
        cnt3 += (a3 > 0.0f) ? 1 : 0;                                        \
    } while (0)

// ring over one strided stream: full 11-chunks unconditional; tail via
// unrolled break-loop (round-7 proven form).
__device__ __forceinline__ void ring_run(
    const ulonglong2* __restrict__ p, int n, int d,
    const unsigned long long w2[KSMAX], unsigned long long bias2,
    float& max0, float& max1, float& max2, float& max3,
    int& cnt0, int& cnt1, int& cnt2, int& cnt3)
{
    unsigned long long y01[KSMAX], y23[KSMAX];
#pragma unroll
    for (int j = 0; j < 10; j++) {
        const ulonglong2 v = p[j * d];
        y01[j] = v.x;
        y23[j] = v.y;
    }
    const ulonglong2* ptr = p + 10 * d;

    while (n >= KSMAX) {
#pragma unroll
        for (int u = 0; u < KSMAX; u++) RING_TRIP(u);
        n -= KSMAX;
    }
#pragma unroll
    for (int u = 0; u < KSMAX - 1; u++) {
        if (u >= n) break;      // near-uniform within warp (sorted work)
        RING_TRIP(u);
    }
}

// ---- main kernel: 16 lanes per (batch-quad, kernel); lane s owns outputs
// [s*L/16, (s+1)*L/16) in flattened (phase, q) order -> exact balance.
__global__ __launch_bounds__(TPB, 5) void rocket_main_kernel(
    const float* __restrict__ x,
    const float* __restrict__ W,
    const float* __restrict__ Bias,
    const int*   __restrict__ base,
    const int*   __restrict__ dil,
    const int*   __restrict__ lo,
    float*       __restrict__ out)
{
    __shared__ ulonglong2 sh[SH_LEN];   // 32KB: lanes (b0,b1 | b2,b3) packed
    const int b0  = 4 * blockIdx.y;
    const int tid = threadIdx.x;
    const int padmax = g_padmax;

    for (int i = tid; i < SH_LEN; i += TPB) sh[i] = make_ulonglong2(0ull, 0ull);
    __syncthreads();
    for (int i = tid; i < SEQ; i += TPB) {
        unsigned long long p01, p23;
        PACK2(p01, x[(b0 + 0) * SEQ + i], x[(b0 + 1) * SEQ + i]);
        PACK2(p23, x[(b0 + 2) * SEQ + i], x[(b0 + 3) * SEQ + i]);
        sh[padmax + i] = make_ulonglong2(p01, p23);
    }
    __syncthreads();

    const int idx  = blockIdx.x * TPB + tid;     // 0 .. 16*NK-1 exactly
    const int slot = idx >> 4;
    const int s    = idx & 15;
    const int k    = g_perm[NK - 1 - slot];      // largest-d first

    unsigned long long w2[KSMAX];
#pragma unroll
    for (int j = 0; j < KSMAX; j++) {
        const float wj = W[k * KSMAX + j];
        PACK2(w2[j], wj, wj);
    }
    const float bias = Bias[k];
    unsigned long long bias2;
    PACK2(bias2, bias, bias);
    const int bs = base[k];
    const int d  = dil[k];
    const int L  = lo[k];

    // per-kernel phase geometry: nq(r) = q0+1 for r<=rem else q0
    const int q0  = (L - 1) / d;
    const int rem = (L - 1) - q0 * d;

    // lane output range [c_lo, c_hi) in flattened (phase,q) order
    const int c_lo = (s * L) >> 4;
    const int c_hi = ((s + 1) * L) >> 4;

    // locate start (r, q) with cumulative-outputs-before == c_lo
    int r, q;
    {
        const int np  = q0 + 1;
        const int thr = (rem + 1) * np;
        if (c_lo < thr) { r = c_lo / np; q = c_lo - r * np; }
        else {
            const int c2 = c_lo - thr;
            const int rr = c2 / q0;
            r = rem + 1 + rr;
            q = c2 - rr * q0;
        }
    }

    float max0 = -INFINITY, max1 = -INFINITY, max2 = -INFINITY, max3 = -INFINITY;
    int   cnt0 = 0, cnt1 = 0, cnt2 = 0, cnt3 = 0;

    int left = c_hi - c_lo;
    while (left > 0) {
        const int nq_r = (r <= rem) ? (q0 + 1) : q0;
        const int n = min(nq_r - q, left);
        ring_run(sh + bs + r + q * d, n, d, w2, bias2,
                 max0, max1, max2, max3, cnt0, cnt1, cnt2, cnt3);
        left -= n;
        ++r;
        q = 0;
    }

    // combine the 16-lane group
    const unsigned mask = 0xffffffffu;
#pragma unroll
    for (int o = 1; o <= 8; o <<= 1) {
        max0 = fmaxf(max0, __shfl_xor_sync(mask, max0, o));
        max1 = fmaxf(max1, __shfl_xor_sync(mask, max1, o));
        max2 = fmaxf(max2, __shfl_xor_sync(mask, max2, o));
        max3 = fmaxf(max3, __shfl_xor_sync(mask, max3, o));
        cnt0 += __shfl_xor_sync(mask, cnt0, o);
        cnt1 += __shfl_xor_sync(mask, cnt1, o);
        cnt2 += __shfl_xor_sync(mask, cnt2, o);
        cnt3 += __shfl_xor_sync(mask, cnt3, o);
    }

    if (s == 0) {
        const float invL = 1.0f / (float)L;
        float2* o0 = (float2*)(out + (size_t)(b0 + 0) * (2 * NK) + 2 * k);
        float2* o1 = (float2*)(out + (size_t)(b0 + 1) * (2 * NK) + 2 * k);
        float2* o2 = (float2*)(out + (size_t)(b0 + 2) * (2 * NK) + 2 * k);
        float2* o3 = (float2*)(out + (size_t)(b0 + 3) * (2 * NK) + 2 * k);
        *o0 = make_float2(max0, (float)cnt0 * invL);
        *o1 = make_float2(max1, (float)cnt1 * invL);
        *o2 = make_float2(max2, (float)cnt2 * invL);
        *o3 = make_float2(max3, (float)cnt3 * invL);
    }
}

extern "C" void kernel_launch(void* const* d_in, const int* in_sizes, int n_in,
                              void* d_out, int out_size) {
    const float* x    = (const float*)d_in[0];
    const float* Wt   = (const float*)d_in[1];
    const float* Bias = (const float*)d_in[2];
    const int*   base = (const int*)d_in[3];
    const int*   dil  = (const int*)d_in[4];
    const int*   lo   = (const int*)d_in[5];
    float* out = (float*)d_out;

    prep_fused_kernel<<<1, PREP_T>>>(base, dil, lo);

    const int nblk = (GL * NK) / TPB;   // 1250 exactly
    dim3 grid(nblk, 2);
    rocket_main_kernel<<<grid, TPB>>>(x, Wt, Bias, base, dil, lo, out);
}

// round 11
// speedup vs baseline: 1.5548x; 1.1635x over previous
#include <cuda_runtime.h>
#include <math.h>

#define NK      10000
#define SEQ     512
#define KSMAX   11
#define SH_LEN  2048     // max read index proven <= ~1886
#define TPB     128
#define GL      8        // lanes per (batch-pair, kernel)
#define PREP_T  1024
#define PBINS   6144     // key = clamp(d,0,95)*64 + min(L>>4,63)

__device__ int g_padmax;
__device__ int g_perm[NK];

// packed fp32x2 helpers (sm_103a)
#define FMA2(acc, ww, yy) \
    asm("fma.rn.f32x2 %0, %1, %2, %0;" : "+l"(acc) : "l"(ww), "l"(yy))
#define UNPACK2(lo, hi, in) \
    asm("mov.b64 {%0, %1}, %2;" : "=f"(lo), "=f"(hi) : "l"(in))
#define PACK2(out, lo, hi) \
    asm("mov.b64 %0, {%1, %2};" : "=l"(out) : "f"(lo), "f"(hi))

__device__ __forceinline__ unsigned smem_u32(const void* p) {
    unsigned a;
    asm("{ .reg .u64 t; cvta.to.shared.u64 t, %1; cvt.u32.u64 %0, t; }"
        : "=r"(a) : "l"(p));
    return a;
}

__device__ __forceinline__ int sort_key(int d, int L) {
    if (d < 0) d = 0;
    if (d > 95) d = 95;
    int lb = L >> 4;
    if (lb < 0) lb = 0;
    if (lb > 63) lb = 63;
    return d * 64 + lb;
}

// ---- single fused prep kernel: padmax + counting sort by (dil, lo-bucket) ----
__global__ __launch_bounds__(PREP_T) void prep_fused_kernel(
    const int* __restrict__ base,
    const int* __restrict__ dil,
    const int* __restrict__ lo)
{
    __shared__ int sbins[PBINS];
    __shared__ int spart[PREP_T];
    const int tid = threadIdx.x;

    int m = 0;
    for (int i = tid; i < NK; i += PREP_T) m = max(m, base[i]);
#pragma unroll
    for (int o = 16; o > 0; o >>= 1) m = max(m, __shfl_xor_sync(0xffffffffu, m, o));
    if ((tid & 31) == 0) spart[tid >> 5] = m;
    __syncthreads();
    if (tid == 0) {
        int mm = 0;
        for (int w = 0; w < PREP_T / 32; w++) mm = max(mm, spart[w]);
        g_padmax = mm;
    }

    for (int i = tid; i < PBINS; i += PREP_T) sbins[i] = 0;
    __syncthreads();

    for (int i = tid; i < NK; i += PREP_T)
        atomicAdd(&sbins[sort_key(dil[i], lo[i])], 1);
    __syncthreads();

    int s = 0;
#pragma unroll
    for (int j = 0; j < 6; j++) s += sbins[tid * 6 + j];
    spart[tid] = s;
    __syncthreads();
    for (int off = 1; off < PREP_T; off <<= 1) {
        int v = spart[tid];
        int u = (tid >= off) ? spart[tid - off] : 0;
        __syncthreads();
        spart[tid] = v + u;
        __syncthreads();
    }
    int run = (tid > 0) ? spart[tid - 1] : 0;
#pragma unroll
    for (int j = 0; j < 6; j++) {
        int c = sbins[tid * 6 + j];
        sbins[tid * 6 + j] = run;
        run += c;
    }
    __syncthreads();

    for (int i = tid; i < NK; i += PREP_T) {
        int pos = atomicAdd(&sbins[sort_key(dil[i], lo[i])], 1);
        g_perm[pos] = i;
    }
}

// one ring trip at static rotation u:
// 1 LDS.64 + 11 FFMA2 (22 fp32 FMA) + 2 FMNMX + 2 sign-accum + 1 IADD
#define RING_TRIP(u)                                                        \
    do {                                                                    \
        unsigned long long nv;                                              \
        asm("ld.shared.b64 %0, [%1];" : "=l"(nv) : "r"(addr));              \
        addr += step;                                                       \
        y[(10 + (u)) % KSMAX] = nv;                                         \
        unsigned long long acc = bias2;                                     \
        _Pragma("unroll")                                                   \
        for (int j = 0; j < KSMAX; j++)                                     \
            FMA2(acc, w2[j], y[((u) + j) % KSMAX]);                         \
        float a0, a1;                                                       \
        UNPACK2(a0, a1, acc);                                               \
        max0 = fmaxf(max0, a0);                                             \
        max1 = fmaxf(max1, a1);                                             \
        neg0 += (__float_as_int(a0) >> 31);   /* -1 per negative */         \
        neg1 += (__float_as_int(a1) >> 31);                                 \
    } while (0)

// ring over one strided stream: full 11-chunks unconditional; tail via
// unrolled break-loop (round-7 proven form). addr is a raw 32-bit shared addr.
__device__ __forceinline__ void ring_run(
    unsigned addr, int n, unsigned step,
    const unsigned long long w2[KSMAX], unsigned long long bias2,
    float& max0, float& max1, int& neg0, int& neg1)
{
    unsigned long long y[KSMAX];
#pragma unroll
    for (int j = 0; j < 10; j++) {
        asm("ld.shared.b64 %0, [%1];" : "=l"(y[j]) : "r"(addr));
        addr += step;
    }

    while (n >= KSMAX) {
#pragma unroll
        for (int u = 0; u < KSMAX; u++) RING_TRIP(u);
        n -= KSMAX;
    }
#pragma unroll
    for (int u = 0; u < KSMAX - 1; u++) {
        if (u >= n) break;      // near-uniform within warp (sorted work)
        RING_TRIP(u);
    }
}

// ---- main kernel: 8 lanes per (batch-pair, kernel); lane s owns outputs
// [s*L/8, (s+1)*L/8) in flattened (phase, q) order -> exact balance.
__global__ __launch_bounds__(TPB, 7) void rocket_main_kernel(
    const float* __restrict__ x,
    const float* __restrict__ W,
    const float* __restrict__ Bias,
    const int*   __restrict__ base,
    const int*   __restrict__ dil,
    const int*   __restrict__ lo,
    float*       __restrict__ out)
{
    __shared__ unsigned long long sh[SH_LEN];   // 16KB: (b0,b1) packed
    const int b0  = 2 * blockIdx.y;
    const int tid = threadIdx.x;
    const int padmax = g_padmax;

    for (int i = tid; i < SH_LEN; i += TPB) sh[i] = 0ull;
    __syncthreads();
    for (int i = tid; i < SEQ; i += TPB) {
        unsigned long long p01;
        PACK2(p01, x[(b0 + 0) * SEQ + i], x[(b0 + 1) * SEQ + i]);
        sh[padmax + i] = p01;
    }
    __syncthreads();

    const unsigned sbase = smem_u32(sh);

    const int idx  = blockIdx.x * TPB + tid;     // 0 .. 8*NK-1 exactly
    const int slot = idx >> 3;
    const int s    = idx & 7;
    const int k    = g_perm[NK - 1 - slot];      // largest-d first

    unsigned long long w2[KSMAX];
#pragma unroll
    for (int j = 0; j < KSMAX; j++) {
        const float wj = W[k * KSMAX + j];
        PACK2(w2[j], wj, wj);
    }
    const float bias = Bias[k];
    unsigned long long bias2;
    PACK2(bias2, bias, bias);
    const int bs = base[k];
    const int d  = dil[k];
    const int L  = lo[k];
    const unsigned step = (unsigned)d * 8u;

    // per-kernel phase geometry: nq(r) = q0+1 for r<=rem else q0
    const int q0  = (L - 1) / d;
    const int rem = (L - 1) - q0 * d;

    // lane output range [c_lo, c_hi) in flattened (phase,q) order
    const int c_lo = (s * L) >> 3;
    const int c_hi = ((s + 1) * L) >> 3;

    // locate start (r, q) with cumulative-outputs-before == c_lo
    int r, q;
    {
        const int np  = q0 + 1;
        const int thr = (rem + 1) * np;
        if (c_lo < thr) { r = c_lo / np; q = c_lo - r * np; }
        else {
            const int c2 = c_lo - thr;
            const int rr = c2 / q0;
            r = rem + 1 + rr;
            q = c2 - rr * q0;
        }
    }

    float max0 = -INFINITY, max1 = -INFINITY;
    int   neg0 = 0, neg1 = 0;     // accumulate -1 per negative output

    int left = c_hi - c_lo;
    while (left > 0) {
        const int nq_r = (r <= rem) ? (q0 + 1) : q0;
        const int n = min(nq_r - q, left);
        const unsigned addr = sbase + (unsigned)(bs + r + q * d) * 8u;
        ring_run(addr, n, step, w2, bias2, max0, max1, neg0, neg1);
        left -= n;
        ++r;
        q = 0;
    }

    // combine the 8-lane group
    const unsigned mask = 0xffffffffu;
#pragma unroll
    for (int o = 1; o <= 4; o <<= 1) {
        max0 = fmaxf(max0, __shfl_xor_sync(mask, max0, o));
        max1 = fmaxf(max1, __shfl_xor_sync(mask, max1, o));
        neg0 += __shfl_xor_sync(mask, neg0, o);
        neg1 += __shfl_xor_sync(mask, neg1, o);
    }

    if (s == 0) {
        const float invL = 1.0f / (float)L;
        // positives = L + sum(neg) (neg holds -count_of_negatives; zeros ~measure 0)
        const float ppv0 = (float)(L + neg0) * invL;
        const float ppv1 = (float)(L + neg1) * invL;
        float2* o0 = (float2*)(out + (size_t)(b0 + 0) * (2 * NK) + 2 * k);
        float2* o1 = (float2*)(out + (size_t)(b0 + 1) * (2 * NK) + 2 * k);
        *o0 = make_float2(max0, ppv0);
        *o1 = make_float2(max1, ppv1);
    }
}

extern "C" void kernel_launch(void* const* d_in, const int* in_sizes, int n_in,
                              void* d_out, int out_size) {
    const float* x    = (const float*)d_in[0];
    const float* Wt   = (const float*)d_in[1];
    const float* Bias = (const float*)d_in[2];
    const int*   base = (const int*)d_in[3];
    const int*   dil  = (const int*)d_in[4];
    const int*   lo   = (const int*)d_in[5];
    float* out = (float*)d_out;

    prep_fused_kernel<<<1, PREP_T>>>(base, dil, lo);

    const int nblk = (GL * NK) / TPB;   // 625 exactly
    dim3 grid(nblk, 4);
    rocket_main_kernel<<<grid, TPB>>>(x, Wt, Bias, base, dil, lo, out);
}